// round 1
// baseline (speedup 1.0000x reference)
#include <cuda_runtime.h>
#include <math.h>
#include <stdint.h>

// Problem constants
#define BATCH 8
#define CH    256
#define NQ    2048
#define MPTS  4096
#define KNN   10

static __device__ float g_Yqk[(size_t)BATCH * CH * NQ];
static __device__ float g_Yv [(size_t)BATCH * CH * NQ];
static __device__ float g_attn[(size_t)BATCH * NQ * NQ];
static __device__ float g_colsum[BATCH * NQ];
static __device__ float g_dbuf[(size_t)BATCH * CH * NQ];
static __device__ float g_feat[(size_t)BATCH * CH * NQ];
static __device__ float g_query[(size_t)BATCH * 3 * NQ];

// ---------------------------------------------------------------------------
// Tiled fp32 GEMM: 128x128 block tile, BK=16, 256 threads, 8x8 per thread.
// TRANSA=false: A is row-major MxK (A[m*lda+k]).
// TRANSA=true : A is stored KxM   (A[k*lda+m]) i.e. we compute A^T * B.
// MODE 0: C = acc
// MODE 1: C = acc + vec1[row]                        (bias)
// MODE 2: C = xres - acc / (1e-9 + vec1[col])        (x - x_r with colsum norm)
// MODE 3: C = xres + relu((acc+vec1[row])*s*gamma[row] + beta[row])  (BN+res)
// All dims are multiples of the tiles -> no bounds checks.
// ---------------------------------------------------------------------------
#define GBM 128
#define GBN 128
#define GBK 16

template<bool TRANSA, int MODE>
__global__ __launch_bounds__(256)
void gemm_kernel(const float* __restrict__ A, size_t sA,
                 const float* __restrict__ B, size_t sB,
                 float* __restrict__ Cout, size_t sC,
                 int M, int N, int K, int lda, int ldb, int ldc,
                 const float* __restrict__ xres, size_t sX,
                 const float* __restrict__ vec1, size_t sV,
                 const float* __restrict__ gamma,
                 const float* __restrict__ beta)
{
    const int b = blockIdx.z;
    A += (size_t)b * sA;
    B += (size_t)b * sB;
    Cout += (size_t)b * sC;
    const float* Xr = xres ? xres + (size_t)b * sX : nullptr;
    const float* V1 = vec1 ? vec1 + (size_t)b * sV : nullptr;

    __shared__ float As[GBK][GBM + 4];
    __shared__ float Bs[GBK][GBN + 4];

    const int tid = threadIdx.x;
    const int tm = tid >> 4;   // 0..15
    const int tn = tid & 15;   // 0..15
    const int row0 = blockIdx.y * GBM;
    const int col0 = blockIdx.x * GBN;

    float acc[8][8];
#pragma unroll
    for (int i = 0; i < 8; i++)
#pragma unroll
        for (int j = 0; j < 8; j++) acc[i][j] = 0.f;

    for (int k0 = 0; k0 < K; k0 += GBK) {
        // ---- load A tile ----
        if (TRANSA) {
#pragma unroll
            for (int i = 0; i < 2; i++) {
                int ff = tid + i * 256;          // 512 float4 total
                int kr = ff >> 5;                // 0..15
                int mc = (ff & 31) * 4;          // 0..124
                float4 v = *(const float4*)&A[(size_t)(k0 + kr) * lda + row0 + mc];
                *(float4*)&As[kr][mc] = v;
            }
        } else {
#pragma unroll
            for (int i = 0; i < 2; i++) {
                int ff = tid + i * 256;
                int r  = ff >> 2;                // 0..127
                int kc = (ff & 3) * 4;           // 0,4,8,12
                float4 v = *(const float4*)&A[(size_t)(row0 + r) * lda + k0 + kc];
                As[kc + 0][r] = v.x;
                As[kc + 1][r] = v.y;
                As[kc + 2][r] = v.z;
                As[kc + 3][r] = v.w;
            }
        }
        // ---- load B tile ----
#pragma unroll
        for (int i = 0; i < 2; i++) {
            int ff = tid + i * 256;
            int kr = ff >> 5;
            int nc = (ff & 31) * 4;
            float4 v = *(const float4*)&B[(size_t)(k0 + kr) * ldb + col0 + nc];
            *(float4*)&Bs[kr][nc] = v;
        }
        __syncthreads();

#pragma unroll
        for (int kk = 0; kk < GBK; kk++) {
            float a[8], bb[8];
            *(float4*)&a[0]  = *(float4*)&As[kk][tm * 8];
            *(float4*)&a[4]  = *(float4*)&As[kk][tm * 8 + 4];
            *(float4*)&bb[0] = *(float4*)&Bs[kk][tn * 8];
            *(float4*)&bb[4] = *(float4*)&Bs[kk][tn * 8 + 4];
#pragma unroll
            for (int i = 0; i < 8; i++)
#pragma unroll
                for (int j = 0; j < 8; j++)
                    acc[i][j] = fmaf(a[i], bb[j], acc[i][j]);
        }
        __syncthreads();
    }

    const float bnscale = 0.9999950000374996f;  // 1/sqrt(1+1e-5)
#pragma unroll
    for (int i = 0; i < 8; i++) {
        int r = row0 + tm * 8 + i;
        float rowbias = 0.f, g = 0.f, be = 0.f;
        if (MODE == 1 || MODE == 3) rowbias = V1[r];
        if (MODE == 3) { g = gamma[r]; be = beta[r]; }
#pragma unroll
        for (int j = 0; j < 8; j++) {
            int c = col0 + tn * 8 + j;
            float v = acc[i][j];
            if (MODE == 1) v += rowbias;
            if (MODE == 2) v = Xr[(size_t)r * ldc + c] - v / (1e-9f + V1[c]);
            if (MODE == 3) {
                v = (v + rowbias) * bnscale * g + be;
                v = Xr[(size_t)r * ldc + c] + fmaxf(v, 0.f);
            }
            Cout[(size_t)r * ldc + c] = v;
        }
    }
}

// ---------------------------------------------------------------------------
// Row softmax over attn rows (in place). One block per row, 256 threads x 8.
// ---------------------------------------------------------------------------
__global__ __launch_bounds__(256)
void softmax_rows(float* __restrict__ attn)
{
    float* row = attn + (size_t)blockIdx.x * NQ;
    const int t = threadIdx.x;
    float v[8];
    float mx = -1e30f;
#pragma unroll
    for (int i = 0; i < 8; i++) {
        v[i] = row[t + i * 256];
        mx = fmaxf(mx, v[i]);
    }
    __shared__ float red[8];
    __shared__ float red2[8];
#pragma unroll
    for (int off = 16; off; off >>= 1)
        mx = fmaxf(mx, __shfl_xor_sync(0xffffffffu, mx, off));
    if ((t & 31) == 0) red[t >> 5] = mx;
    __syncthreads();
    mx = red[0];
#pragma unroll
    for (int i = 1; i < 8; i++) mx = fmaxf(mx, red[i]);

    float s = 0.f;
#pragma unroll
    for (int i = 0; i < 8; i++) {
        v[i] = __expf(v[i] - mx);
        s += v[i];
    }
#pragma unroll
    for (int off = 16; off; off >>= 1)
        s += __shfl_xor_sync(0xffffffffu, s, off);
    if ((t & 31) == 0) red2[t >> 5] = s;
    __syncthreads();
    s = red2[0];
#pragma unroll
    for (int i = 1; i < 8; i++) s += red2[i];
    float inv = 1.f / s;
#pragma unroll
    for (int i = 0; i < 8; i++) row[t + i * 256] = v[i] * inv;
}

__global__ void zero_kernel(float* __restrict__ p, int n)
{
    int i = blockIdx.x * blockDim.x + threadIdx.x;
    if (i < n) p[i] = 0.f;
}

// colsum[b][m] = sum_n attn[b][n][m]; grid (B, NQ/256, NQ/256)
__global__ __launch_bounds__(256)
void colsum_kernel(const float* __restrict__ attn, float* __restrict__ cs)
{
    const int b = blockIdx.x;
    const int m = blockIdx.y * 256 + threadIdx.x;
    const int n0 = blockIdx.z * 256;
    const float* p = attn + ((size_t)b * NQ + n0) * NQ + m;
    float s = 0.f;
#pragma unroll 8
    for (int n = 0; n < 256; n++) s += p[(size_t)n * NQ];
    atomicAdd(&cs[b * NQ + m], s);
}

// query[b][j][n] = sum_c W_proj[j][c] * feat[b][c][n] + b_proj[j]
__global__ __launch_bounds__(256)
void query_kernel(const float* __restrict__ feat, const float* __restrict__ Wp,
                  const float* __restrict__ bp, float* __restrict__ q)
{
    const int n = blockIdx.x * 256 + threadIdx.x;
    const int b = blockIdx.y;
    const float* f = feat + (size_t)b * CH * NQ + n;
    float a0 = 0.f, a1 = 0.f, a2 = 0.f;
#pragma unroll 4
    for (int c = 0; c < CH; c++) {
        float fv = f[(size_t)c * NQ];
        a0 = fmaf(Wp[c], fv, a0);
        a1 = fmaf(Wp[CH + c], fv, a1);
        a2 = fmaf(Wp[2 * CH + c], fv, a2);
    }
    size_t o = (size_t)b * 3 * NQ + n;
    q[o]          = a0 + bp[0];
    q[o + NQ]     = a1 + bp[1];
    q[o + 2 * NQ] = a2 + bp[2];
}

// ---------------------------------------------------------------------------
// Soft projection: per query, top-10 nearest among 4096 DB points (held in
// shared), softmax(-d2/sigma) weighted average. One warp per query, 8 queries
// per warp per block. grid (BATCH, NQ/64), 256 threads.
// ---------------------------------------------------------------------------
__global__ __launch_bounds__(256)
void softproj_kernel(const float* __restrict__ pc,     // (B,3,M)
                     const float* __restrict__ query,  // (B,3,N)
                     const float* __restrict__ temp,   // scalar
                     float* __restrict__ out)          // (B,3,N)
{
    __shared__ float spx[MPTS];
    __shared__ float spy[MPTS];
    __shared__ float spz[MPTS];

    const int b = blockIdx.x;
    const float* p = pc + (size_t)b * 3 * MPTS;
    for (int i = threadIdx.x; i < MPTS; i += 256) {
        spx[i] = p[i];
        spy[i] = p[MPTS + i];
        spz[i] = p[2 * MPTS + i];
    }
    __syncthreads();

    const float t = temp[0];
    const float sigma = fmaxf(t * t, 1e-4f) + 1e-8f;
    const float invsig = 1.f / sigma;

    const int warp = threadIdx.x >> 5;
    const int lane = threadIdx.x & 31;
    const int qbase = blockIdx.y * 64;

    for (int qq = 0; qq < 8; ++qq) {
        const int n = qbase + warp * 8 + qq;
        const float qx = query[((size_t)b * 3 + 0) * NQ + n];
        const float qy = query[((size_t)b * 3 + 1) * NQ + n];
        const float qz = query[((size_t)b * 3 + 2) * NQ + n];

        float d[KNN];
        int   idx[KNN];
#pragma unroll
        for (int i = 0; i < KNN; i++) { d[i] = 1e30f; idx[i] = 0; }

        for (int m = lane; m < MPTS; m += 32) {
            float dx = spx[m] - qx;
            float dy = spy[m] - qy;
            float dz = spz[m] - qz;
            float dd = fmaf(dx, dx, fmaf(dy, dy, dz * dz));
            if (dd < d[KNN - 1]) {
                d[KNN - 1] = dd; idx[KNN - 1] = m;
#pragma unroll
                for (int j = KNN - 1; j > 0; --j) {
                    if (d[j] < d[j - 1]) {
                        float td = d[j]; d[j] = d[j - 1]; d[j - 1] = td;
                        int ti = idx[j]; idx[j] = idx[j - 1]; idx[j - 1] = ti;
                    }
                }
            }
        }

        // merge: extract global KNN smallest in increasing order
        float wsum = 0.f, ox = 0.f, oy = 0.f, oz = 0.f;
        float dmin = 0.f;
#pragma unroll
        for (int k = 0; k < KNN; k++) {
            float cd = d[0];
            int   ci = idx[0];
#pragma unroll
            for (int off = 16; off; off >>= 1) {
                float od = __shfl_xor_sync(0xffffffffu, cd, off);
                int   oi = __shfl_xor_sync(0xffffffffu, ci, off);
                if (od < cd || (od == cd && oi < ci)) { cd = od; ci = oi; }
            }
            if (k == 0) dmin = cd;
            float w = __expf(-(cd - dmin) * invsig);
            wsum += w;
            ox = fmaf(w, spx[ci], ox);
            oy = fmaf(w, spy[ci], oy);
            oz = fmaf(w, spz[ci], oz);
            bool iwin = (d[0] == cd && idx[0] == ci);
            unsigned bal = __ballot_sync(0xffffffffu, iwin);
            if (lane == (__ffs(bal) - 1)) {
#pragma unroll
                for (int j = 0; j < KNN - 1; j++) { d[j] = d[j + 1]; idx[j] = idx[j + 1]; }
                d[KNN - 1] = 1e30f; idx[KNN - 1] = 0;
            }
        }

        if (lane == 0) {
            float inv = 1.f / wsum;
            out[((size_t)b * 3 + 0) * NQ + n] = ox * inv;
            out[((size_t)b * 3 + 1) * NQ + n] = oy * inv;
            out[((size_t)b * 3 + 2) * NQ + n] = oz * inv;
        }
    }
}

// ---------------------------------------------------------------------------
extern "C" void kernel_launch(void* const* d_in, const int* in_sizes, int n_in,
                              void* d_out, int out_size)
{
    const float* x     = (const float*)d_in[0];
    const float* pc    = (const float*)d_in[1];
    const float* Wqk   = (const float*)d_in[2];
    const float* Wv    = (const float*)d_in[3];
    const float* bv    = (const float*)d_in[4];
    const float* Wt    = (const float*)d_in[5];
    const float* bt    = (const float*)d_in[6];
    const float* gamma = (const float*)d_in[7];
    const float* beta  = (const float*)d_in[8];
    const float* Wp    = (const float*)d_in[9];
    const float* bp    = (const float*)d_in[10];
    const float* temp  = (const float*)d_in[11];
    float* out = (float*)d_out;

    float *Yqk, *Yv, *attn, *colsum, *dbuf, *feat, *query;
    cudaGetSymbolAddress((void**)&Yqk,    g_Yqk);
    cudaGetSymbolAddress((void**)&Yv,     g_Yv);
    cudaGetSymbolAddress((void**)&attn,   g_attn);
    cudaGetSymbolAddress((void**)&colsum, g_colsum);
    cudaGetSymbolAddress((void**)&dbuf,   g_dbuf);
    cudaGetSymbolAddress((void**)&feat,   g_feat);
    cudaGetSymbolAddress((void**)&query,  g_query);

    const size_t CHNQ = (size_t)CH * NQ;
    const size_t NQNQ = (size_t)NQ * NQ;
    dim3 blk(256);
    dim3 gProj(NQ / GBN, CH / GBM, BATCH);   // (16,2,8)
    dim3 gE(NQ / GBN, NQ / GBM, BATCH);      // (16,16,8)

    // Yqk = Wqk @ x   (per batch)
    gemm_kernel<false, 0><<<gProj, blk>>>(Wqk, 0, x, CHNQ, Yqk, CHNQ,
                                          CH, NQ, CH, CH, NQ, NQ,
                                          nullptr, 0, nullptr, 0, nullptr, nullptr);
    // Yv = Wv @ x + bv
    gemm_kernel<false, 1><<<gProj, blk>>>(Wv, 0, x, CHNQ, Yv, CHNQ,
                                          CH, NQ, CH, CH, NQ, NQ,
                                          nullptr, 0, bv, 0, nullptr, nullptr);
    // energy = Yqk^T @ Yqk
    gemm_kernel<true, 0><<<gE, blk>>>(Yqk, CHNQ, Yqk, CHNQ, attn, NQNQ,
                                      NQ, NQ, CH, NQ, NQ, NQ,
                                      nullptr, 0, nullptr, 0, nullptr, nullptr);
    // row softmax in place
    softmax_rows<<<BATCH * NQ, 256>>>(attn);
    // colsum
    zero_kernel<<<(BATCH * NQ + 255) / 256, 256>>>(colsum, BATCH * NQ);
    colsum_kernel<<<dim3(BATCH, NQ / 256, NQ / 256), 256>>>(attn, colsum);
    // dbuf = x - (Yv @ attn) / (1e-9 + colsum)
    gemm_kernel<false, 2><<<gProj, blk>>>(Yv, CHNQ, attn, NQNQ, dbuf, CHNQ,
                                          CH, NQ, NQ, NQ, NQ, NQ,
                                          x, CHNQ, colsum, NQ, nullptr, nullptr);
    // feat = x + relu(BN(Wt @ dbuf + bt))
    gemm_kernel<false, 3><<<gProj, blk>>>(Wt, 0, dbuf, CHNQ, feat, CHNQ,
                                          CH, NQ, CH, CH, NQ, NQ,
                                          x, CHNQ, bt, 0, gamma, beta);
    // query = Wp @ feat + bp
    query_kernel<<<dim3(NQ / 256, BATCH), 256>>>(feat, Wp, bp, query);
    // soft projection
    softproj_kernel<<<dim3(BATCH, NQ / 64), 256>>>(pc, query, temp, out);
}

// round 2
// speedup vs baseline: 1.0001x; 1.0001x over previous
#include <cuda_runtime.h>
#include <math.h>
#include <stdint.h>

// Problem constants
#define BATCH 8
#define CH    256
#define NQ    2048
#define MPTS  4096
#define KNN   10

static __device__ float g_Yqk[(size_t)BATCH * CH * NQ];
static __device__ float g_Yv [(size_t)BATCH * CH * NQ];
static __device__ float g_attn[(size_t)BATCH * NQ * NQ];
static __device__ float g_colsum[BATCH * NQ];
static __device__ float g_dbuf[(size_t)BATCH * CH * NQ];
static __device__ float g_feat[(size_t)BATCH * CH * NQ];
static __device__ float g_query[(size_t)BATCH * 3 * NQ];

// ---------------------------------------------------------------------------
// Tiled fp32 GEMM: 128x128 block tile, BK=16, 256 threads, 8x8 per thread.
// TRANSA=false: A is row-major MxK (A[m*lda+k]).
// TRANSA=true : A is stored KxM   (A[k*lda+m]) i.e. we compute A^T * B.
// MODE 0: C = acc
// MODE 1: C = acc + vec1[row]                        (bias)
// MODE 2: C = xres - acc / (1e-9 + vec1[col])        (x - x_r with colsum norm)
// MODE 3: C = xres + relu((acc+vec1[row])*s*gamma[row] + beta[row])  (BN+res)
// All dims are multiples of the tiles -> no bounds checks.
// ---------------------------------------------------------------------------
#define GBM 128
#define GBN 128
#define GBK 16

template<bool TRANSA, int MODE>
__global__ __launch_bounds__(256)
void gemm_kernel(const float* __restrict__ A, size_t sA,
                 const float* __restrict__ B, size_t sB,
                 float* __restrict__ Cout, size_t sC,
                 int M, int N, int K, int lda, int ldb, int ldc,
                 const float* __restrict__ xres, size_t sX,
                 const float* __restrict__ vec1, size_t sV,
                 const float* __restrict__ gamma,
                 const float* __restrict__ beta)
{
    const int b = blockIdx.z;
    A += (size_t)b * sA;
    B += (size_t)b * sB;
    Cout += (size_t)b * sC;
    const float* Xr = xres ? xres + (size_t)b * sX : nullptr;
    const float* V1 = vec1 ? vec1 + (size_t)b * sV : nullptr;

    __shared__ float As[GBK][GBM + 4];
    __shared__ float Bs[GBK][GBN + 4];

    const int tid = threadIdx.x;
    const int tm = tid >> 4;   // 0..15
    const int tn = tid & 15;   // 0..15
    const int row0 = blockIdx.y * GBM;
    const int col0 = blockIdx.x * GBN;

    float acc[8][8];
#pragma unroll
    for (int i = 0; i < 8; i++)
#pragma unroll
        for (int j = 0; j < 8; j++) acc[i][j] = 0.f;

    for (int k0 = 0; k0 < K; k0 += GBK) {
        // ---- load A tile ----
        if (TRANSA) {
#pragma unroll
            for (int i = 0; i < 2; i++) {
                int ff = tid + i * 256;          // 512 float4 total
                int kr = ff >> 5;                // 0..15
                int mc = (ff & 31) * 4;          // 0..124
                float4 v = *(const float4*)&A[(size_t)(k0 + kr) * lda + row0 + mc];
                *(float4*)&As[kr][mc] = v;
            }
        } else {
#pragma unroll
            for (int i = 0; i < 2; i++) {
                int ff = tid + i * 256;
                int r  = ff >> 2;                // 0..127
                int kc = (ff & 3) * 4;           // 0,4,8,12
                float4 v = *(const float4*)&A[(size_t)(row0 + r) * lda + k0 + kc];
                As[kc + 0][r] = v.x;
                As[kc + 1][r] = v.y;
                As[kc + 2][r] = v.z;
                As[kc + 3][r] = v.w;
            }
        }
        // ---- load B tile ----
#pragma unroll
        for (int i = 0; i < 2; i++) {
            int ff = tid + i * 256;
            int kr = ff >> 5;
            int nc = (ff & 31) * 4;
            float4 v = *(const float4*)&B[(size_t)(k0 + kr) * ldb + col0 + nc];
            *(float4*)&Bs[kr][nc] = v;
        }
        __syncthreads();

#pragma unroll
        for (int kk = 0; kk < GBK; kk++) {
            float a[8], bb[8];
            *(float4*)&a[0]  = *(float4*)&As[kk][tm * 8];
            *(float4*)&a[4]  = *(float4*)&As[kk][tm * 8 + 4];
            *(float4*)&bb[0] = *(float4*)&Bs[kk][tn * 8];
            *(float4*)&bb[4] = *(float4*)&Bs[kk][tn * 8 + 4];
#pragma unroll
            for (int i = 0; i < 8; i++)
#pragma unroll
                for (int j = 0; j < 8; j++)
                    acc[i][j] = fmaf(a[i], bb[j], acc[i][j]);
        }
        __syncthreads();
    }

    const float bnscale = 0.9999950000374996f;  // 1/sqrt(1+1e-5)
#pragma unroll
    for (int i = 0; i < 8; i++) {
        int r = row0 + tm * 8 + i;
        float rowbias = 0.f, g = 0.f, be = 0.f;
        if (MODE == 1 || MODE == 3) rowbias = V1[r];
        if (MODE == 3) { g = gamma[r]; be = beta[r]; }
#pragma unroll
        for (int j = 0; j < 8; j++) {
            int c = col0 + tn * 8 + j;
            float v = acc[i][j];
            if (MODE == 1) v += rowbias;
            if (MODE == 2) v = Xr[(size_t)r * ldc + c] - v / (1e-9f + V1[c]);
            if (MODE == 3) {
                v = (v + rowbias) * bnscale * g + be;
                v = Xr[(size_t)r * ldc + c] + fmaxf(v, 0.f);
            }
            Cout[(size_t)r * ldc + c] = v;
        }
    }
}

// ---------------------------------------------------------------------------
// Row softmax over attn rows (in place). One block per row, 256 threads x 8.
// ---------------------------------------------------------------------------
__global__ __launch_bounds__(256)
void softmax_rows(float* __restrict__ attn)
{
    float* row = attn + (size_t)blockIdx.x * NQ;
    const int t = threadIdx.x;
    float v[8];
    float mx = -1e30f;
#pragma unroll
    for (int i = 0; i < 8; i++) {
        v[i] = row[t + i * 256];
        mx = fmaxf(mx, v[i]);
    }
    __shared__ float red[8];
    __shared__ float red2[8];
#pragma unroll
    for (int off = 16; off; off >>= 1)
        mx = fmaxf(mx, __shfl_xor_sync(0xffffffffu, mx, off));
    if ((t & 31) == 0) red[t >> 5] = mx;
    __syncthreads();
    mx = red[0];
#pragma unroll
    for (int i = 1; i < 8; i++) mx = fmaxf(mx, red[i]);

    float s = 0.f;
#pragma unroll
    for (int i = 0; i < 8; i++) {
        v[i] = __expf(v[i] - mx);
        s += v[i];
    }
#pragma unroll
    for (int off = 16; off; off >>= 1)
        s += __shfl_xor_sync(0xffffffffu, s, off);
    if ((t & 31) == 0) red2[t >> 5] = s;
    __syncthreads();
    s = red2[0];
#pragma unroll
    for (int i = 1; i < 8; i++) s += red2[i];
    float inv = 1.f / s;
#pragma unroll
    for (int i = 0; i < 8; i++) row[t + i * 256] = v[i] * inv;
}

__global__ void zero_kernel(float* __restrict__ p, int n)
{
    int i = blockIdx.x * blockDim.x + threadIdx.x;
    if (i < n) p[i] = 0.f;
}

// colsum[b][m] = sum_n attn[b][n][m]; grid (B, NQ/256, NQ/256)
__global__ __launch_bounds__(256)
void colsum_kernel(const float* __restrict__ attn, float* __restrict__ cs)
{
    const int b = blockIdx.x;
    const int m = blockIdx.y * 256 + threadIdx.x;
    const int n0 = blockIdx.z * 256;
    const float* p = attn + ((size_t)b * NQ + n0) * NQ + m;
    float s = 0.f;
#pragma unroll 8
    for (int n = 0; n < 256; n++) s += p[(size_t)n * NQ];
    atomicAdd(&cs[b * NQ + m], s);
}

// query[b][j][n] = sum_c W_proj[j][c] * feat[b][c][n] + b_proj[j]
__global__ __launch_bounds__(256)
void query_kernel(const float* __restrict__ feat, const float* __restrict__ Wp,
                  const float* __restrict__ bp, float* __restrict__ q)
{
    const int n = blockIdx.x * 256 + threadIdx.x;
    const int b = blockIdx.y;
    const float* f = feat + (size_t)b * CH * NQ + n;
    float a0 = 0.f, a1 = 0.f, a2 = 0.f;
#pragma unroll 4
    for (int c = 0; c < CH; c++) {
        float fv = f[(size_t)c * NQ];
        a0 = fmaf(Wp[c], fv, a0);
        a1 = fmaf(Wp[CH + c], fv, a1);
        a2 = fmaf(Wp[2 * CH + c], fv, a2);
    }
    size_t o = (size_t)b * 3 * NQ + n;
    q[o]          = a0 + bp[0];
    q[o + NQ]     = a1 + bp[1];
    q[o + 2 * NQ] = a2 + bp[2];
}

// ---------------------------------------------------------------------------
// Soft projection: per query, top-10 nearest among 4096 DB points (held in
// shared), softmax(-d2/sigma) weighted average. One warp per query, 8 queries
// per warp per block. grid (BATCH, NQ/64), 256 threads.
// ---------------------------------------------------------------------------
__global__ __launch_bounds__(256)
void softproj_kernel(const float* __restrict__ pc,     // (B,3,M)
                     const float* __restrict__ query,  // (B,3,N)
                     const float* __restrict__ temp,   // scalar
                     float* __restrict__ out)          // (B,3,N)
{
    __shared__ float spx[MPTS];
    __shared__ float spy[MPTS];
    __shared__ float spz[MPTS];

    const int b = blockIdx.x;
    const float* p = pc + (size_t)b * 3 * MPTS;
    for (int i = threadIdx.x; i < MPTS; i += 256) {
        spx[i] = p[i];
        spy[i] = p[MPTS + i];
        spz[i] = p[2 * MPTS + i];
    }
    __syncthreads();

    const float t = temp[0];
    const float sigma = fmaxf(t * t, 1e-4f) + 1e-8f;
    const float invsig = 1.f / sigma;

    const int warp = threadIdx.x >> 5;
    const int lane = threadIdx.x & 31;
    const int qbase = blockIdx.y * 64;

    for (int qq = 0; qq < 8; ++qq) {
        const int n = qbase + warp * 8 + qq;
        const float qx = query[((size_t)b * 3 + 0) * NQ + n];
        const float qy = query[((size_t)b * 3 + 1) * NQ + n];
        const float qz = query[((size_t)b * 3 + 2) * NQ + n];

        float d[KNN];
        int   idx[KNN];
#pragma unroll
        for (int i = 0; i < KNN; i++) { d[i] = 1e30f; idx[i] = 0; }

        for (int m = lane; m < MPTS; m += 32) {
            float dx = spx[m] - qx;
            float dy = spy[m] - qy;
            float dz = spz[m] - qz;
            float dd = fmaf(dx, dx, fmaf(dy, dy, dz * dz));
            if (dd < d[KNN - 1]) {
                d[KNN - 1] = dd; idx[KNN - 1] = m;
#pragma unroll
                for (int j = KNN - 1; j > 0; --j) {
                    if (d[j] < d[j - 1]) {
                        float td = d[j]; d[j] = d[j - 1]; d[j - 1] = td;
                        int ti = idx[j]; idx[j] = idx[j - 1]; idx[j - 1] = ti;
                    }
                }
            }
        }

        // merge: extract global KNN smallest in increasing order
        float wsum = 0.f, ox = 0.f, oy = 0.f, oz = 0.f;
        float dmin = 0.f;
#pragma unroll
        for (int k = 0; k < KNN; k++) {
            float cd = d[0];
            int   ci = idx[0];
#pragma unroll
            for (int off = 16; off; off >>= 1) {
                float od = __shfl_xor_sync(0xffffffffu, cd, off);
                int   oi = __shfl_xor_sync(0xffffffffu, ci, off);
                if (od < cd || (od == cd && oi < ci)) { cd = od; ci = oi; }
            }
            if (k == 0) dmin = cd;
            float w = __expf(-(cd - dmin) * invsig);
            wsum += w;
            ox = fmaf(w, spx[ci], ox);
            oy = fmaf(w, spy[ci], oy);
            oz = fmaf(w, spz[ci], oz);
            bool iwin = (d[0] == cd && idx[0] == ci);
            unsigned bal = __ballot_sync(0xffffffffu, iwin);
            if (lane == (__ffs(bal) - 1)) {
#pragma unroll
                for (int j = 0; j < KNN - 1; j++) { d[j] = d[j + 1]; idx[j] = idx[j + 1]; }
                d[KNN - 1] = 1e30f; idx[KNN - 1] = 0;
            }
        }

        if (lane == 0) {
            float inv = 1.f / wsum;
            out[((size_t)b * 3 + 0) * NQ + n] = ox * inv;
            out[((size_t)b * 3 + 1) * NQ + n] = oy * inv;
            out[((size_t)b * 3 + 2) * NQ + n] = oz * inv;
        }
    }
}

// ---------------------------------------------------------------------------
extern "C" void kernel_launch(void* const* d_in, const int* in_sizes, int n_in,
                              void* d_out, int out_size)
{
    const float* x     = (const float*)d_in[0];
    const float* pc    = (const float*)d_in[1];
    const float* Wqk   = (const float*)d_in[2];
    const float* Wv    = (const float*)d_in[3];
    const float* bv    = (const float*)d_in[4];
    const float* Wt    = (const float*)d_in[5];
    const float* bt    = (const float*)d_in[6];
    const float* gamma = (const float*)d_in[7];
    const float* beta  = (const float*)d_in[8];
    const float* Wp    = (const float*)d_in[9];
    const float* bp    = (const float*)d_in[10];
    const float* temp  = (const float*)d_in[11];
    float* out = (float*)d_out;

    float *Yqk, *Yv, *attn, *colsum, *dbuf, *feat, *query;
    cudaGetSymbolAddress((void**)&Yqk,    g_Yqk);
    cudaGetSymbolAddress((void**)&Yv,     g_Yv);
    cudaGetSymbolAddress((void**)&attn,   g_attn);
    cudaGetSymbolAddress((void**)&colsum, g_colsum);
    cudaGetSymbolAddress((void**)&dbuf,   g_dbuf);
    cudaGetSymbolAddress((void**)&feat,   g_feat);
    cudaGetSymbolAddress((void**)&query,  g_query);

    const size_t CHNQ = (size_t)CH * NQ;
    const size_t NQNQ = (size_t)NQ * NQ;
    dim3 blk(256);
    dim3 gProj(NQ / GBN, CH / GBM, BATCH);   // (16,2,8)
    dim3 gE(NQ / GBN, NQ / GBM, BATCH);      // (16,16,8)

    // Yqk = Wqk @ x   (per batch)
    gemm_kernel<false, 0><<<gProj, blk>>>(Wqk, 0, x, CHNQ, Yqk, CHNQ,
                                          CH, NQ, CH, CH, NQ, NQ,
                                          nullptr, 0, nullptr, 0, nullptr, nullptr);
    // Yv = Wv @ x + bv
    gemm_kernel<false, 1><<<gProj, blk>>>(Wv, 0, x, CHNQ, Yv, CHNQ,
                                          CH, NQ, CH, CH, NQ, NQ,
                                          nullptr, 0, bv, 0, nullptr, nullptr);
    // energy = Yqk^T @ Yqk
    gemm_kernel<true, 0><<<gE, blk>>>(Yqk, CHNQ, Yqk, CHNQ, attn, NQNQ,
                                      NQ, NQ, CH, NQ, NQ, NQ,
                                      nullptr, 0, nullptr, 0, nullptr, nullptr);
    // row softmax in place
    softmax_rows<<<BATCH * NQ, 256>>>(attn);
    // colsum
    zero_kernel<<<(BATCH * NQ + 255) / 256, 256>>>(colsum, BATCH * NQ);
    colsum_kernel<<<dim3(BATCH, NQ / 256, NQ / 256), 256>>>(attn, colsum);
    // dbuf = x - (Yv @ attn) / (1e-9 + colsum)
    gemm_kernel<false, 2><<<gProj, blk>>>(Yv, CHNQ, attn, NQNQ, dbuf, CHNQ,
                                          CH, NQ, NQ, NQ, NQ, NQ,
                                          x, CHNQ, colsum, NQ, nullptr, nullptr);
    // feat = x + relu(BN(Wt @ dbuf + bt))
    gemm_kernel<false, 3><<<gProj, blk>>>(Wt, 0, dbuf, CHNQ, feat, CHNQ,
                                          CH, NQ, CH, CH, NQ, NQ,
                                          x, CHNQ, bt, 0, gamma, beta);
    // query = Wp @ feat + bp
    query_kernel<<<dim3(NQ / 256, BATCH), 256>>>(feat, Wp, bp, query);
    // soft projection
    softproj_kernel<<<dim3(BATCH, NQ / 64), 256>>>(pc, query, temp, out);
}